// round 1
// baseline (speedup 1.0000x reference)
#include <cuda_runtime.h>

#define N_NODES 2048
#define F_IN    64
#define H_DIM   16
#define O_DIM   8
#define FPB     2      // features per block in k_fsum

// -------- scratch (no allocations allowed) --------
__device__ float g_fsums[N_NODES * O_DIM];   // [N, O] f-branch sums
__device__ float g_alpha_pos;
__device__ float g_alpha_neg;
__device__ float g_beta;
__device__ int   g_fastflag;

// ============================================================================
// Kernel 1: zero f_sums scratch (graph is replayed -> must reset every launch)
// and collapse the m-MLP to an affine-per-sign form when biases are zero:
//   m(d) = a_pos*max(d,0) + a_neg*min(d,0) + mb3
// Valid because relu(d*w + 0) = d*max(w,0) for d>=0 (d*min(w,0) for d<0).
// ============================================================================
__global__ void k_prep(const float* __restrict__ mW1, const float* __restrict__ mb1,
                       const float* __restrict__ mW2, const float* __restrict__ mb2,
                       const float* __restrict__ mW3, const float* __restrict__ mb3)
{
    int idx = blockIdx.x * blockDim.x + threadIdx.x;
    if (idx < N_NODES * O_DIM) g_fsums[idx] = 0.0f;

    if (blockIdx.x == 0 && threadIdx.x == 0) {
        bool zeros = true;
        #pragma unroll
        for (int k = 0; k < H_DIM; k++)
            zeros = zeros && (mb1[k] == 0.0f) && (mb2[k] == 0.0f);

        float ap = 0.0f, an = 0.0f;
        for (int g = 0; g < H_DIM; g++) {
            float cp = 0.0f, cn = 0.0f;
            for (int h = 0; h < H_DIM; h++) {
                float w2 = mW2[g * H_DIM + h];
                cp += w2 * fmaxf(mW1[h], 0.0f);
                cn += w2 * fminf(mW1[h], 0.0f);
            }
            ap += mW3[g] * fmaxf(cp, 0.0f);
            an += mW3[g] * fminf(cn, 0.0f);
        }
        g_alpha_pos = ap;
        g_alpha_neg = an;
        g_beta      = mb3[0];
        g_fastflag  = zeros ? 1 : 0;
    }
}

// ============================================================================
// Kernel 2: per-feature f-MLPs (1->16->16->8), summed over features.
// grid = (F_IN/FPB, N_NODES/256), block = 256 (one node per thread).
// Weights for this block's FPB features staged in smem (broadcast reads).
// Cross-feature-group reduction via atomicAdd into g_fsums.
// ============================================================================
__global__ void __launch_bounds__(256)
k_fsum(const float* __restrict__ x,
       const float* __restrict__ fW1, const float* __restrict__ fb1,
       const float* __restrict__ fW2, const float* __restrict__ fb2,
       const float* __restrict__ fW3, const float* __restrict__ fb3)
{
    __shared__ float sW1[FPB * H_DIM];
    __shared__ float sB1[FPB * H_DIM];
    __shared__ float sW2[FPB * H_DIM * H_DIM];
    __shared__ float sB2[FPB * H_DIM];
    __shared__ float sW3[FPB * O_DIM * H_DIM];
    __shared__ float sB3[FPB * O_DIM];

    const int f0  = blockIdx.x * FPB;
    const int tid = threadIdx.x;

    for (int i = tid; i < FPB * H_DIM; i += blockDim.x) {
        sW1[i] = fW1[f0 * H_DIM + i];
        sB1[i] = fb1[f0 * H_DIM + i];
        sB2[i] = fb2[f0 * H_DIM + i];
    }
    for (int i = tid; i < FPB * H_DIM * H_DIM; i += blockDim.x)
        sW2[i] = fW2[f0 * H_DIM * H_DIM + i];
    for (int i = tid; i < FPB * O_DIM * H_DIM; i += blockDim.x)
        sW3[i] = fW3[f0 * O_DIM * H_DIM + i];
    for (int i = tid; i < FPB * O_DIM; i += blockDim.x)
        sB3[i] = fb3[f0 * O_DIM + i];
    __syncthreads();

    const int n = blockIdx.y * blockDim.x + tid;

    float acc[O_DIM];
    #pragma unroll
    for (int o = 0; o < O_DIM; o++) acc[o] = 0.0f;

    #pragma unroll
    for (int ff = 0; ff < FPB; ff++) {
        const float xv = x[n * F_IN + f0 + ff];

        float h1[H_DIM];
        #pragma unroll
        for (int k = 0; k < H_DIM; k++)
            h1[k] = fmaxf(fmaf(xv, sW1[ff * H_DIM + k], sB1[ff * H_DIM + k]), 0.0f);

        float h2[H_DIM];
        #pragma unroll
        for (int g = 0; g < H_DIM; g++) {
            float s = sB2[ff * H_DIM + g];
            #pragma unroll
            for (int k = 0; k < H_DIM; k++)
                s = fmaf(sW2[ff * H_DIM * H_DIM + g * H_DIM + k], h1[k], s);
            h2[g] = fmaxf(s, 0.0f);
        }

        #pragma unroll
        for (int o = 0; o < O_DIM; o++) {
            float s = sB3[ff * O_DIM + o];
            #pragma unroll
            for (int k = 0; k < H_DIM; k++)
                s = fmaf(sW3[ff * O_DIM * H_DIM + o * H_DIM + k], h2[k], s);
            acc[o] += s;
        }
    }

    #pragma unroll
    for (int o = 0; o < O_DIM; o++)
        atomicAdd(&g_fsums[n * O_DIM + o], acc[o]);
}

// ============================================================================
// Kernel 3: pred[i,:] = sum_j ( m(d[i,j]) / norm[i,j] ) * f_sums[j,:]
// One block per row i, 256 threads, 8 j's per thread. Memory-bound:
// streams 16 KB of d + norm per block; f_sums (64 KB) is L1-resident.
// Fast path uses the collapsed m(d); slow path evaluates the full MLP
// (correct for arbitrary biases, never taken for this problem's inputs).
// ============================================================================
__global__ void __launch_bounds__(256)
k_main(const float* __restrict__ dmat, const float* __restrict__ nmat,
       const float* __restrict__ mW1, const float* __restrict__ mb1,
       const float* __restrict__ mW2, const float* __restrict__ mb2,
       const float* __restrict__ mW3, const float* __restrict__ mb3,
       float* __restrict__ out)
{
    __shared__ float sred[8][O_DIM];
    __shared__ float sw1[H_DIM], sb1[H_DIM], sw2[H_DIM * H_DIM], sb2[H_DIM], sw3[H_DIM];

    const int i   = blockIdx.x;
    const int tid = threadIdx.x;

    const float* __restrict__ drow = dmat + (size_t)i * N_NODES;
    const float* __restrict__ nrow = nmat + (size_t)i * N_NODES;

    float acc[O_DIM];
    #pragma unroll
    for (int o = 0; o < O_DIM; o++) acc[o] = 0.0f;

    const int fast = g_fastflag;

    if (fast) {
        const float ap = g_alpha_pos, an = g_alpha_neg, beta = g_beta;
        #pragma unroll
        for (int it = 0; it < N_NODES / 256; it++) {
            const int j = it * 256 + tid;
            const float d = drow[j];
            const float m = fmaf(ap, fmaxf(d, 0.0f), fmaf(an, fminf(d, 0.0f), beta));
            const float w = __fdividef(m, nrow[j]);
            const float4* fsp = (const float4*)(g_fsums + j * O_DIM);
            const float4 a = fsp[0];
            const float4 b = fsp[1];
            acc[0] = fmaf(w, a.x, acc[0]); acc[1] = fmaf(w, a.y, acc[1]);
            acc[2] = fmaf(w, a.z, acc[2]); acc[3] = fmaf(w, a.w, acc[3]);
            acc[4] = fmaf(w, b.x, acc[4]); acc[5] = fmaf(w, b.y, acc[5]);
            acc[6] = fmaf(w, b.z, acc[6]); acc[7] = fmaf(w, b.w, acc[7]);
        }
    } else {
        // honest fallback: full per-pair m-MLP
        if (tid < H_DIM) {
            sw1[tid] = mW1[tid]; sb1[tid] = mb1[tid];
            sb2[tid] = mb2[tid]; sw3[tid] = mW3[tid];
        }
        if (tid < H_DIM * H_DIM) sw2[tid] = mW2[tid];
        __syncthreads();
        const float b3v = mb3[0];

        for (int it = 0; it < N_NODES / 256; it++) {
            const int j = it * 256 + tid;
            const float d = drow[j];
            float h1[H_DIM];
            #pragma unroll
            for (int k = 0; k < H_DIM; k++)
                h1[k] = fmaxf(fmaf(d, sw1[k], sb1[k]), 0.0f);
            float m = b3v;
            #pragma unroll
            for (int g = 0; g < H_DIM; g++) {
                float s = sb2[g];
                #pragma unroll
                for (int k = 0; k < H_DIM; k++)
                    s = fmaf(sw2[g * H_DIM + k], h1[k], s);
                m = fmaf(sw3[g], fmaxf(s, 0.0f), m);
            }
            const float w = __fdividef(m, nrow[j]);
            const float4* fsp = (const float4*)(g_fsums + j * O_DIM);
            const float4 a = fsp[0];
            const float4 b = fsp[1];
            acc[0] = fmaf(w, a.x, acc[0]); acc[1] = fmaf(w, a.y, acc[1]);
            acc[2] = fmaf(w, a.z, acc[2]); acc[3] = fmaf(w, a.w, acc[3]);
            acc[4] = fmaf(w, b.x, acc[4]); acc[5] = fmaf(w, b.y, acc[5]);
            acc[6] = fmaf(w, b.z, acc[6]); acc[7] = fmaf(w, b.w, acc[7]);
        }
    }

    // block reduction: warp shuffle then smem across 8 warps
    #pragma unroll
    for (int o = 0; o < O_DIM; o++) {
        #pragma unroll
        for (int off = 16; off > 0; off >>= 1)
            acc[o] += __shfl_xor_sync(0xFFFFFFFFu, acc[o], off);
    }
    const int warp = tid >> 5;
    const int lane = tid & 31;
    if (lane == 0) {
        #pragma unroll
        for (int o = 0; o < O_DIM; o++) sred[warp][o] = acc[o];
    }
    __syncthreads();
    if (tid < O_DIM) {
        float s = 0.0f;
        #pragma unroll
        for (int wp = 0; wp < 8; wp++) s += sred[wp][tid];
        out[i * O_DIM + tid] = s;
    }
}

// ============================================================================
// launch
// ============================================================================
extern "C" void kernel_launch(void* const* d_in, const int* in_sizes, int n_in,
                              void* d_out, int out_size)
{
    const float* x   = (const float*)d_in[0];
    const float* dm  = (const float*)d_in[1];
    const float* nm  = (const float*)d_in[2];
    const float* fW1 = (const float*)d_in[3];
    const float* fb1 = (const float*)d_in[4];
    const float* fW2 = (const float*)d_in[5];
    const float* fb2 = (const float*)d_in[6];
    const float* fW3 = (const float*)d_in[7];
    const float* fb3 = (const float*)d_in[8];
    const float* mW1 = (const float*)d_in[9];
    const float* mb1 = (const float*)d_in[10];
    const float* mW2 = (const float*)d_in[11];
    const float* mb2 = (const float*)d_in[12];
    const float* mW3 = (const float*)d_in[13];
    const float* mb3 = (const float*)d_in[14];
    float* out = (float*)d_out;

    k_prep<<<64, 256>>>(mW1, mb1, mW2, mb2, mW3, mb3);

    dim3 gf(F_IN / FPB, N_NODES / 256);
    k_fsum<<<gf, 256>>>(x, fW1, fb1, fW2, fb2, fW3, fb3);

    k_main<<<N_NODES, 256>>>(dm, nm, mW1, mb1, mW2, mb2, mW3, mb3, out);
}

// round 2
// speedup vs baseline: 1.3229x; 1.3229x over previous
#include <cuda_runtime.h>

#define N_NODES 2048
#define F_IN    64
#define H_DIM   16
#define O_DIM   8

// -------- scratch (no allocations allowed) --------
__device__ float g_fsums[N_NODES * O_DIM];   // [N, O] f-branch sums

// ============================================================================
// Kernel 1: f-branch. grid=32, block=256.
// Block handles 64 nodes; thread (nl = tid&63, fq = tid>>6) covers feature
// quarter [fq*16, fq*16+16) for node nl. Cross-quarter reduce via smem.
//
// Fast path (all f-biases zero, true for this problem): each per-feature
// 1->16->16->8 relu MLP with zero biases collapses EXACTLY to
//   fx[o] = max(x,0)*A+[f,o] + min(x,0)*A-[f,o]
//   A+[f,o] = sum_g fW3[f,o,g]*max(c+_g,0), c+_g = sum_h fW2[f,g,h]*max(fW1[f,h],0)
// (A- with mins). Fold is computed per-block (cheap, weights L2-hot).
// Slow path: honest full MLP chain (never taken here, kept for correctness).
// ============================================================================
__global__ void __launch_bounds__(256)
k_fsum(const float* __restrict__ x,
       const float* __restrict__ fW1, const float* __restrict__ fb1,
       const float* __restrict__ fW2, const float* __restrict__ fb2,
       const float* __restrict__ fW3, const float* __restrict__ fb3)
{
    __shared__ float sA[F_IN][16];       // [f][0..7]=A+, [f][8..15]=A-
    __shared__ float sred[256][O_DIM];

    const int tid = threadIdx.x;

    // ---- runtime guard: all f-biases zero? ----
    int nz = 0;
    for (int i = tid; i < F_IN * H_DIM; i += 256)
        nz |= (fb1[i] != 0.0f) | (fb2[i] != 0.0f);
    for (int i = tid; i < F_IN * O_DIM; i += 256)
        nz |= (fb3[i] != 0.0f);
    const int any_nz = __syncthreads_or(nz);

    const int nl = tid & 63;
    const int fq = tid >> 6;             // 0..3
    const int n  = blockIdx.x * 64 + nl;

    float acc[O_DIM];
    #pragma unroll
    for (int o = 0; o < O_DIM; o++) acc[o] = 0.0f;

    if (!any_nz) {
        // ---- fold: thread t handles f = t>>2, g-range part*4..part*4+3 ----
        {
            const int f    = tid >> 2;
            const int part = tid & 3;
            float cp[4], cn[4];
            #pragma unroll
            for (int gi = 0; gi < 4; gi++) {
                const int g = part * 4 + gi;
                float sp = 0.0f, sn = 0.0f;
                #pragma unroll
                for (int h = 0; h < H_DIM; h++) {
                    const float w2 = __ldg(fW2 + (f * H_DIM + g) * H_DIM + h);
                    const float w1 = __ldg(fW1 + f * H_DIM + h);
                    sp = fmaf(w2, fmaxf(w1, 0.0f), sp);
                    sn = fmaf(w2, fminf(w1, 0.0f), sn);
                }
                cp[gi] = fmaxf(sp, 0.0f);
                cn[gi] = fminf(sn, 0.0f);
            }
            float ap[O_DIM], an[O_DIM];
            #pragma unroll
            for (int o = 0; o < O_DIM; o++) {
                float sa = 0.0f, sb = 0.0f;
                #pragma unroll
                for (int gi = 0; gi < 4; gi++) {
                    const float w3 = __ldg(fW3 + (f * O_DIM + o) * H_DIM + part * 4 + gi);
                    sa = fmaf(w3, cp[gi], sa);
                    sb = fmaf(w3, cn[gi], sb);
                }
                ap[o] = sa; an[o] = sb;
            }
            #pragma unroll
            for (int o = 0; o < O_DIM; o++) {
                ap[o] += __shfl_xor_sync(0xFFFFFFFFu, ap[o], 1);
                ap[o] += __shfl_xor_sync(0xFFFFFFFFu, ap[o], 2);
                an[o] += __shfl_xor_sync(0xFFFFFFFFu, an[o], 1);
                an[o] += __shfl_xor_sync(0xFFFFFFFFu, an[o], 2);
            }
            if (part == 0) {
                #pragma unroll
                for (int o = 0; o < O_DIM; o++) {
                    sA[f][o]     = ap[o];
                    sA[f][8 + o] = an[o];
                }
            }
        }
        __syncthreads();

        // ---- relu-split GEMV over this thread's 16 features ----
        const float4* xr = (const float4*)(x + n * F_IN + fq * 16);
        float xv[16];
        #pragma unroll
        for (int q = 0; q < 4; q++) {
            const float4 v = __ldg(xr + q);
            xv[q*4+0] = v.x; xv[q*4+1] = v.y; xv[q*4+2] = v.z; xv[q*4+3] = v.w;
        }
        #pragma unroll
        for (int ff = 0; ff < 16; ff++) {
            const int   f  = fq * 16 + ff;
            const float xp = fmaxf(xv[ff], 0.0f);
            const float xn = fminf(xv[ff], 0.0f);
            #pragma unroll
            for (int o = 0; o < O_DIM; o++)
                acc[o] = fmaf(xp, sA[f][o], fmaf(xn, sA[f][8 + o], acc[o]));
        }
    } else {
        // ---- honest fallback: full per-feature MLP chain ----
        for (int ff = 0; ff < 16; ff++) {
            const int   f  = fq * 16 + ff;
            const float xv = x[n * F_IN + f];
            float h1[H_DIM];
            #pragma unroll
            for (int k = 0; k < H_DIM; k++)
                h1[k] = fmaxf(fmaf(xv, __ldg(fW1 + f*H_DIM + k), __ldg(fb1 + f*H_DIM + k)), 0.0f);
            float h2[H_DIM];
            #pragma unroll
            for (int g = 0; g < H_DIM; g++) {
                float s = __ldg(fb2 + f*H_DIM + g);
                #pragma unroll
                for (int k = 0; k < H_DIM; k++)
                    s = fmaf(__ldg(fW2 + (f*H_DIM + g)*H_DIM + k), h1[k], s);
                h2[g] = fmaxf(s, 0.0f);
            }
            #pragma unroll
            for (int o = 0; o < O_DIM; o++) {
                float s = __ldg(fb3 + f*O_DIM + o);
                #pragma unroll
                for (int k = 0; k < H_DIM; k++)
                    s = fmaf(__ldg(fW3 + (f*O_DIM + o)*H_DIM + k), h2[k], s);
                acc[o] += s;
            }
        }
    }

    // ---- reduce 4 feature-quarters per node, direct write (no atomics) ----
    #pragma unroll
    for (int o = 0; o < O_DIM; o++) sred[tid][o] = acc[o];
    __syncthreads();
    if (tid < 64) {
        #pragma unroll
        for (int o = 0; o < O_DIM; o++) {
            const float s = sred[tid][o] + sred[tid + 64][o]
                          + sred[tid + 128][o] + sred[tid + 192][o];
            g_fsums[(blockIdx.x * 64 + tid) * O_DIM + o] = s;
        }
    }
}

// ============================================================================
// Helper: full scalar m-MLP (fallback path only)
// ============================================================================
__device__ __forceinline__ float m_eval_full(float d,
    const float* sw1, const float* sb1, const float* sw2,
    const float* sb2, const float* sw3, float b3)
{
    float h1[H_DIM];
    #pragma unroll
    for (int k = 0; k < H_DIM; k++)
        h1[k] = fmaxf(fmaf(d, sw1[k], sb1[k]), 0.0f);
    float m = b3;
    #pragma unroll
    for (int g = 0; g < H_DIM; g++) {
        float s = sb2[g];
        #pragma unroll
        for (int k = 0; k < H_DIM; k++)
            s = fmaf(sw2[g * H_DIM + k], h1[k], s);
        m = fmaf(sw3[g], fmaxf(s, 0.0f), m);
    }
    return m;
}

// ============================================================================
// Kernel 2: pred[i,:] = sum_j ( m(d[i,j]) / norm[i,j] ) * f_sums[j,:]
// grid=256 blocks, 8 rows per block (amortizes f_sums reads 8x ->
// f_sums L2 traffic drops 134MB -> 16MB). HBM-bound on 33.5MB of d+norm.
// m-MLP fold computed per-block by warp 0 (weights L2-hot, ~600cyc).
// Thread handles 4 consecutive j (float4 loads), 2 j-tiles.
// ============================================================================
__global__ void __launch_bounds__(256)
k_main(const float* __restrict__ dmat, const float* __restrict__ nmat,
       const float* __restrict__ mW1, const float* __restrict__ mb1,
       const float* __restrict__ mW2, const float* __restrict__ mb2,
       const float* __restrict__ mW3, const float* __restrict__ mb3,
       float* __restrict__ out)
{
    __shared__ float s_ap, s_an, s_beta;
    __shared__ int   s_fast;
    __shared__ float sred[8][64];
    __shared__ float sw1[H_DIM], sb1v[H_DIM], sw2[H_DIM * H_DIM], sb2v[H_DIM], sw3[H_DIM];

    const int tid = threadIdx.x;

    // ---- warp 0: fold m-MLP + zero-bias check ----
    if (tid < 32) {
        const int g = tid & 15;
        float cp = 0.0f, cn = 0.0f;
        #pragma unroll
        for (int h = 0; h < H_DIM; h++) {
            const float w2 = __ldg(mW2 + g * H_DIM + h);
            const float w1 = __ldg(mW1 + h);
            cp = fmaf(w2, fmaxf(w1, 0.0f), cp);
            cn = fmaf(w2, fminf(w1, 0.0f), cn);
        }
        const float w3 = __ldg(mW3 + g);
        float ap = w3 * fmaxf(cp, 0.0f);
        float an = w3 * fminf(cn, 0.0f);
        #pragma unroll
        for (int off = 8; off > 0; off >>= 1) {
            ap += __shfl_xor_sync(0xFFFFFFFFu, ap, off);
            an += __shfl_xor_sync(0xFFFFFFFFu, an, off);
        }
        int z = (__ldg(mb1 + g) == 0.0f) & (__ldg(mb2 + g) == 0.0f);
        z = __all_sync(0xFFFFFFFFu, z);
        if (tid == 0) { s_ap = ap; s_an = an; s_beta = __ldg(mb3); s_fast = z; }
    }
    __syncthreads();

    const int i0 = blockIdx.x * 8;

    float acc[8][O_DIM];
    #pragma unroll
    for (int r = 0; r < 8; r++)
        #pragma unroll
        for (int o = 0; o < O_DIM; o++) acc[r][o] = 0.0f;

    if (s_fast) {
        const float ap = s_ap, an = s_an, be = s_beta;
        #pragma unroll
        for (int jt = 0; jt < 2; jt++) {
            const int j0 = jt * 1024 + tid * 4;
            // f_sums for 4 j's: 8 float4 (L1/L2-resident table)
            float4 fs[8];
            const float4* fp = (const float4*)(g_fsums + j0 * O_DIM);
            #pragma unroll
            for (int q = 0; q < 8; q++) fs[q] = fp[q];

            #pragma unroll
            for (int r = 0; r < 8; r++) {
                const float4 d4 = *(const float4*)(dmat + (size_t)(i0 + r) * N_NODES + j0);
                const float4 n4 = *(const float4*)(nmat + (size_t)(i0 + r) * N_NODES + j0);
                const float w0 = __fdividef(fmaf(ap, fmaxf(d4.x, 0.f), fmaf(an, fminf(d4.x, 0.f), be)), n4.x);
                const float w1 = __fdividef(fmaf(ap, fmaxf(d4.y, 0.f), fmaf(an, fminf(d4.y, 0.f), be)), n4.y);
                const float w2 = __fdividef(fmaf(ap, fmaxf(d4.z, 0.f), fmaf(an, fminf(d4.z, 0.f), be)), n4.z);
                const float w3 = __fdividef(fmaf(ap, fmaxf(d4.w, 0.f), fmaf(an, fminf(d4.w, 0.f), be)), n4.w);
                #pragma unroll
                for (int o = 0; o < 4; o++) {
                    acc[r][o]   = fmaf(w0, (&fs[0].x)[o], acc[r][o]);
                    acc[r][4+o] = fmaf(w0, (&fs[1].x)[o], acc[r][4+o]);
                    acc[r][o]   = fmaf(w1, (&fs[2].x)[o], acc[r][o]);
                    acc[r][4+o] = fmaf(w1, (&fs[3].x)[o], acc[r][4+o]);
                    acc[r][o]   = fmaf(w2, (&fs[4].x)[o], acc[r][o]);
                    acc[r][4+o] = fmaf(w2, (&fs[5].x)[o], acc[r][4+o]);
                    acc[r][o]   = fmaf(w3, (&fs[6].x)[o], acc[r][o]);
                    acc[r][4+o] = fmaf(w3, (&fs[7].x)[o], acc[r][4+o]);
                }
            }
        }
    } else {
        // ---- honest fallback: full per-pair m-MLP ----
        if (tid < H_DIM) {
            sw1[tid]  = mW1[tid]; sb1v[tid] = mb1[tid];
            sb2v[tid] = mb2[tid]; sw3[tid]  = mW3[tid];
        }
        sw2[tid] = mW2[tid];   // 256 threads cover 256 weights
        __syncthreads();
        const float b3v = mb3[0];

        for (int jt = 0; jt < 2; jt++) {
            const int j0 = jt * 1024 + tid * 4;
            float4 fs[8];
            const float4* fp = (const float4*)(g_fsums + j0 * O_DIM);
            #pragma unroll
            for (int q = 0; q < 8; q++) fs[q] = fp[q];

            for (int r = 0; r < 8; r++) {
                const float4 d4 = *(const float4*)(dmat + (size_t)(i0 + r) * N_NODES + j0);
                const float4 n4 = *(const float4*)(nmat + (size_t)(i0 + r) * N_NODES + j0);
                float w[4];
                w[0] = __fdividef(m_eval_full(d4.x, sw1, sb1v, sw2, sb2v, sw3, b3v), n4.x);
                w[1] = __fdividef(m_eval_full(d4.y, sw1, sb1v, sw2, sb2v, sw3, b3v), n4.y);
                w[2] = __fdividef(m_eval_full(d4.z, sw1, sb1v, sw2, sb2v, sw3, b3v), n4.z);
                w[3] = __fdividef(m_eval_full(d4.w, sw1, sb1v, sw2, sb2v, sw3, b3v), n4.w);
                #pragma unroll
                for (int q = 0; q < 4; q++) {
                    #pragma unroll
                    for (int o = 0; o < 4; o++) {
                        acc[r][o]   = fmaf(w[q], (&fs[q*2].x)[o],   acc[r][o]);
                        acc[r][4+o] = fmaf(w[q], (&fs[q*2+1].x)[o], acc[r][4+o]);
                    }
                }
            }
        }
    }

    // ---- block reduction: warp butterfly, then 8 warps via smem ----
    #pragma unroll
    for (int r = 0; r < 8; r++)
        #pragma unroll
        for (int o = 0; o < O_DIM; o++)
            #pragma unroll
            for (int off = 16; off > 0; off >>= 1)
                acc[r][o] += __shfl_xor_sync(0xFFFFFFFFu, acc[r][o], off);

    const int warp = tid >> 5;
    const int lane = tid & 31;
    if (lane == 0) {
        #pragma unroll
        for (int r = 0; r < 8; r++)
            #pragma unroll
            for (int o = 0; o < O_DIM; o++)
                sred[warp][r * O_DIM + o] = acc[r][o];
    }
    __syncthreads();
    if (tid < 64) {
        float s = 0.0f;
        #pragma unroll
        for (int w = 0; w < 8; w++) s += sred[w][tid];
        const int r = tid >> 3;
        const int o = tid & 7;
        out[(i0 + r) * O_DIM + o] = s;
    }
}

// ============================================================================
// launch — 2 kernels, no prep kernel, no atomics, no scratch zeroing needed
// ============================================================================
extern "C" void kernel_launch(void* const* d_in, const int* in_sizes, int n_in,
                              void* d_out, int out_size)
{
    const float* x   = (const float*)d_in[0];
    const float* dm  = (const float*)d_in[1];
    const float* nm  = (const float*)d_in[2];
    const float* fW1 = (const float*)d_in[3];
    const float* fb1 = (const float*)d_in[4];
    const float* fW2 = (const float*)d_in[5];
    const float* fb2 = (const float*)d_in[6];
    const float* fW3 = (const float*)d_in[7];
    const float* fb3 = (const float*)d_in[8];
    const float* mW1 = (const float*)d_in[9];
    const float* mb1 = (const float*)d_in[10];
    const float* mW2 = (const float*)d_in[11];
    const float* mb2 = (const float*)d_in[12];
    const float* mW3 = (const float*)d_in[13];
    const float* mb3 = (const float*)d_in[14];
    float* out = (float*)d_out;

    k_fsum<<<32, 256>>>(x, fW1, fb1, fW2, fb2, fW3, fb3);
    k_main<<<256, 256>>>(dm, nm, mW1, mb1, mW2, mb2, mW3, mb3, out);
}